// round 1
// baseline (speedup 1.0000x reference)
#include <cuda_runtime.h>
#include <cuda_bf16.h>
#include <math.h>

// ---------------- problem constants ----------------
#define T_DIM 4096
#define D_DIM 2048
#define H_DIM 16
#define NOPE 128
#define ROPE 64
#define VD 128
#define KV_RANK 512
#define HEAD 192               // NOPE + ROPE
#define Q_RANK 1536
#define B_DIM 2
#define S_DIM 2048
#define SCALE_F 0.072168783648703220563f   // 192^-0.5
#define EPS_F 1e-6f

// ---------------- scratch (device globals; no allocation allowed) ----------------
__device__ float g_qa  [(long long)T_DIM * Q_RANK];
__device__ float g_qan [(long long)T_DIM * Q_RANK];
__device__ float g_q   [(long long)T_DIM * H_DIM * HEAD];
__device__ float g_ckv [(long long)T_DIM * (KV_RANK + ROPE)];
__device__ float g_ckvn[(long long)T_DIM * KV_RANK];
__device__ float g_kv  [(long long)T_DIM * H_DIM * (NOPE + VD)];
__device__ float g_key [(long long)T_DIM * H_DIM * HEAD];
__device__ float g_scores[(long long)B_DIM * H_DIM * S_DIM * S_DIM]; // 536 MB
__device__ float g_attn[(long long)T_DIM * H_DIM * VD];

// ---------------- generic batched SGEMM: C = A @ B (or A @ B^T) ----------------
// BM=BN=128, BK=8, 256 threads, 8x8 microtile. M must be a multiple of 128,
// K a multiple of 8 (true for all call sites). N guarded when GUARD_N.
#define BM 128
#define BN 128
#define BK 8

template<bool TRANS_B, bool GUARD_N>
__global__ void __launch_bounds__(256)
sgemm_kernel(const float* __restrict__ A, const float* __restrict__ B,
             float* __restrict__ C,
             int M, int N, int K, int lda, int ldb, int ldc,
             long long sAb, long long sAh,
             long long sBb, long long sBh,
             long long sCb, long long sCh, int Hdim)
{
    int z  = blockIdx.z;
    int bb = z / Hdim, hh = z % Hdim;
    A += bb * sAb + hh * sAh;
    B += bb * sBb + hh * sBh;
    C += bb * sCb + hh * sCh;

    int m0 = blockIdx.y * BM;
    int n0 = blockIdx.x * BN;

    __shared__ float As[BK][BM];
    __shared__ float Bs[BK][BN];

    int tid = threadIdx.x;
    int tx = tid & 15;       // 0..15
    int ty = tid >> 4;       // 0..15

    float acc[8][8];
#pragma unroll
    for (int i = 0; i < 8; i++)
#pragma unroll
        for (int j = 0; j < 8; j++) acc[i][j] = 0.f;

    int arow = tid >> 1;             // 0..127 (m within tile)
    int acol = (tid & 1) * 4;        // 0 or 4  (k within tile)
    int brow, bcol;
    if (TRANS_B) { brow = tid >> 1; bcol = (tid & 1) * 4; }   // brow = n, bcol = k
    else         { brow = tid >> 5; bcol = (tid & 31) * 4; }  // brow = k, bcol = n

    for (int k0 = 0; k0 < K; k0 += BK) {
        // A tile (no guard: M%128==0, K%8==0)
        float4 av = *(const float4*)(A + (long long)(m0 + arow) * lda + (k0 + acol));
        As[acol + 0][arow] = av.x;
        As[acol + 1][arow] = av.y;
        As[acol + 2][arow] = av.z;
        As[acol + 3][arow] = av.w;

        if (TRANS_B) {
            float4 bv = make_float4(0.f, 0.f, 0.f, 0.f);
            if (!GUARD_N || (n0 + brow) < N)
                bv = *(const float4*)(B + (long long)(n0 + brow) * ldb + (k0 + bcol));
            Bs[bcol + 0][brow] = bv.x;
            Bs[bcol + 1][brow] = bv.y;
            Bs[bcol + 2][brow] = bv.z;
            Bs[bcol + 3][brow] = bv.w;
        } else {
            float4 bv = make_float4(0.f, 0.f, 0.f, 0.f);
            if (!GUARD_N || (n0 + bcol) < N)    // N%4==0 at guarded sites
                bv = *(const float4*)(B + (long long)(k0 + brow) * ldb + (n0 + bcol));
            *(float4*)&Bs[brow][bcol] = bv;
        }
        __syncthreads();

#pragma unroll
        for (int kk = 0; kk < BK; kk++) {
            float a[8], b[8];
            *(float4*)&a[0] = *(const float4*)&As[kk][ty * 8];
            *(float4*)&a[4] = *(const float4*)&As[kk][ty * 8 + 4];
            *(float4*)&b[0] = *(const float4*)&Bs[kk][tx * 8];
            *(float4*)&b[4] = *(const float4*)&Bs[kk][tx * 8 + 4];
#pragma unroll
            for (int i = 0; i < 8; i++)
#pragma unroll
                for (int j = 0; j < 8; j++)
                    acc[i][j] += a[i] * b[j];
        }
        __syncthreads();
    }

#pragma unroll
    for (int i = 0; i < 8; i++) {
        int m = m0 + ty * 8 + i;
#pragma unroll
        for (int j = 0; j < 8; j += 4) {
            int n = n0 + tx * 8 + j;
            if (!GUARD_N || n < N) {
                float4 cv = make_float4(acc[i][j], acc[i][j + 1], acc[i][j + 2], acc[i][j + 3]);
                *(float4*)(C + (long long)m * ldc + n) = cv;
            }
        }
    }
}

// ---------------- rmsnorm (row-wise) ----------------
__global__ void rmsnorm_kernel(const float* __restrict__ x, const float* __restrict__ w,
                               float* __restrict__ y, int N, int ldx, int ldy)
{
    long long row = blockIdx.x;
    const float* xr = x + row * ldx;
    float* yr = y + row * ldy;
    int tid = threadIdx.x;

    float ss = 0.f;
    for (int i = tid; i < N; i += 256) { float v = xr[i]; ss += v * v; }

    __shared__ float red[256];
    red[tid] = ss; __syncthreads();
#pragma unroll
    for (int s = 128; s > 0; s >>= 1) {
        if (tid < s) red[tid] += red[tid + s];
        __syncthreads();
    }
    float sc = rsqrtf(red[0] / (float)N + EPS_F);
    for (int i = tid; i < N; i += 256) yr[i] = xr[i] * sc * w[i];
}

// ---------------- in-place RoPE on q (last 64 of each head) ----------------
__global__ void rope_q_kernel(float* __restrict__ q,
                              const float* __restrict__ cosp,
                              const float* __restrict__ sinp)
{
    int t = blockIdx.x, h = blockIdx.y, i = threadIdx.x;  // 32 threads
    float* pe = q + ((long long)t * H_DIM + h) * HEAD + NOPE;
    float e = pe[2 * i], o = pe[2 * i + 1];
    float c = cosp[t * 32 + i], s = sinp[t * 32 + i];
    __syncwarp();
    pe[i]      = e * c - o * s;
    pe[32 + i] = o * c + e * s;
}

// ---------------- build key[T,H,192] = concat(kv_nope, rope(k_pe)) ----------------
__global__ void build_key_kernel(const float* __restrict__ kv,
                                 const float* __restrict__ ckv,
                                 const float* __restrict__ cosp,
                                 const float* __restrict__ sinp,
                                 float* __restrict__ key)
{
    int t = blockIdx.x, h = blockIdx.y, tid = threadIdx.x;  // 128 threads
    float* kr = key + ((long long)t * H_DIM + h) * HEAD;
    kr[tid] = kv[(long long)t * (H_DIM * (NOPE + VD)) + h * (NOPE + VD) + tid];
    if (tid < 32) {
        const float* pe = ckv + (long long)t * (KV_RANK + ROPE) + KV_RANK;
        float e = pe[2 * tid], o = pe[2 * tid + 1];
        float c = cosp[t * 32 + tid], s = sinp[t * 32 + tid];
        kr[NOPE + tid]      = e * c - o * s;
        kr[NOPE + 32 + tid] = o * c + e * s;
    }
}

// ---------------- causal softmax over scores (in place, masked -> 0) ----------------
__global__ void softmax_kernel(float* __restrict__ scores)
{
    long long row = blockIdx.x;            // (b*H + h)*S + q
    int q = (int)(row % S_DIM);
    float* p = scores + row * (long long)S_DIM;
    int tid = threadIdx.x;
    __shared__ float red[256];

    float mx = -3.4e38f;
    for (int i = tid; i <= q; i += 256) mx = fmaxf(mx, p[i]);
    red[tid] = mx; __syncthreads();
#pragma unroll
    for (int s = 128; s > 0; s >>= 1) {
        if (tid < s) red[tid] = fmaxf(red[tid], red[tid + s]);
        __syncthreads();
    }
    mx = red[0] * SCALE_F;
    __syncthreads();

    float sum = 0.f;
    for (int i = tid; i <= q; i += 256) {
        float e = expf(p[i] * SCALE_F - mx);
        p[i] = e;
        sum += e;
    }
    red[tid] = sum; __syncthreads();
#pragma unroll
    for (int s = 128; s > 0; s >>= 1) {
        if (tid < s) red[tid] += red[tid + s];
        __syncthreads();
    }
    float inv = 1.0f / red[0];
    for (int i = tid; i <= q; i += 256) p[i] *= inv;
    for (int i = q + 1 + tid; i < S_DIM; i += 256) p[i] = 0.f;
}

// ---------------- launch ----------------
extern "C" void kernel_launch(void* const* d_in, const int* in_sizes, int n_in,
                              void* d_out, int out_size)
{
    const float* hidden   = (const float*)d_in[0];
    const float* cosp     = (const float*)d_in[1];
    const float* sinp     = (const float*)d_in[2];
    const float* w_q_a    = (const float*)d_in[3];
    const float* q_a_ln_w = (const float*)d_in[4];
    const float* w_q_b    = (const float*)d_in[5];
    const float* w_kv_a   = (const float*)d_in[6];
    const float* kv_a_ln_w= (const float*)d_in[7];
    const float* w_kv_b   = (const float*)d_in[8];
    const float* w_o      = (const float*)d_in[9];
    float* out = (float*)d_out;

    float *p_qa, *p_qan, *p_q, *p_ckv, *p_ckvn, *p_kv, *p_key, *p_scores, *p_attn;
    cudaGetSymbolAddress((void**)&p_qa,     g_qa);
    cudaGetSymbolAddress((void**)&p_qan,    g_qan);
    cudaGetSymbolAddress((void**)&p_q,      g_q);
    cudaGetSymbolAddress((void**)&p_ckv,    g_ckv);
    cudaGetSymbolAddress((void**)&p_ckvn,   g_ckvn);
    cudaGetSymbolAddress((void**)&p_kv,     g_kv);
    cudaGetSymbolAddress((void**)&p_key,    g_key);
    cudaGetSymbolAddress((void**)&p_scores, g_scores);
    cudaGetSymbolAddress((void**)&p_attn,   g_attn);

    const long long Z0 = 0;

    // 1. qa = hidden @ w_q_a   [4096,2048]@[2048,1536]
    sgemm_kernel<false,false><<<dim3(Q_RANK/BN, T_DIM/BM, 1), 256>>>(
        hidden, w_q_a, p_qa, T_DIM, Q_RANK, D_DIM, D_DIM, Q_RANK, Q_RANK,
        Z0,Z0,Z0,Z0,Z0,Z0, 1);

    // 2. rmsnorm(qa)
    rmsnorm_kernel<<<T_DIM, 256>>>(p_qa, q_a_ln_w, p_qan, Q_RANK, Q_RANK, Q_RANK);

    // 3. q = qan @ w_q_b   [4096,1536]@[1536,3072]
    sgemm_kernel<false,false><<<dim3((H_DIM*HEAD)/BN, T_DIM/BM, 1), 256>>>(
        p_qan, w_q_b, p_q, T_DIM, H_DIM*HEAD, Q_RANK, Q_RANK, H_DIM*HEAD, H_DIM*HEAD,
        Z0,Z0,Z0,Z0,Z0,Z0, 1);

    // 4. RoPE on q (in place)
    rope_q_kernel<<<dim3(T_DIM, H_DIM), 32>>>(p_q, cosp, sinp);

    // 5. ckv = hidden @ w_kv_a  [4096,2048]@[2048,576]  (N=576 guarded)
    sgemm_kernel<false,true><<<dim3((KV_RANK+ROPE+BN-1)/BN, T_DIM/BM, 1), 256>>>(
        hidden, w_kv_a, p_ckv, T_DIM, KV_RANK+ROPE, D_DIM, D_DIM, KV_RANK+ROPE, KV_RANK+ROPE,
        Z0,Z0,Z0,Z0,Z0,Z0, 1);

    // 6. rmsnorm(ckv[:, :512])
    rmsnorm_kernel<<<T_DIM, 256>>>(p_ckv, kv_a_ln_w, p_ckvn, KV_RANK, KV_RANK+ROPE, KV_RANK);

    // 7. kv = ckvn @ w_kv_b   [4096,512]@[512,4096]
    sgemm_kernel<false,false><<<dim3((H_DIM*(NOPE+VD))/BN, T_DIM/BM, 1), 256>>>(
        p_ckvn, w_kv_b, p_kv, T_DIM, H_DIM*(NOPE+VD), KV_RANK,
        KV_RANK, H_DIM*(NOPE+VD), H_DIM*(NOPE+VD),
        Z0,Z0,Z0,Z0,Z0,Z0, 1);

    // 8. build key
    build_key_kernel<<<dim3(T_DIM, H_DIM), 128>>>(p_kv, p_ckv, cosp, sinp, p_key);

    // 9. scores[b,h] = Q[b,:,h,:] @ K[b,:,h,:]^T   (batched NT, K=192)
    sgemm_kernel<true,false><<<dim3(S_DIM/BN, S_DIM/BM, B_DIM*H_DIM), 256>>>(
        p_q, p_key, p_scores, S_DIM, S_DIM, HEAD,
        H_DIM*HEAD, H_DIM*HEAD, S_DIM,
        (long long)S_DIM * H_DIM * HEAD, (long long)HEAD,          // A strides (b,h)
        (long long)S_DIM * H_DIM * HEAD, (long long)HEAD,          // B strides (b,h)
        (long long)H_DIM * S_DIM * S_DIM, (long long)S_DIM * S_DIM,// C strides (b,h)
        H_DIM);

    // 10. causal softmax (scale inside)
    softmax_kernel<<<B_DIM * H_DIM * S_DIM, 256>>>(p_scores);

    // 11. attn[b,:,h,:] = P[b,h] @ V[b,:,h,:]   (V read from kv at offset 128, stride 256)
    sgemm_kernel<false,false><<<dim3(VD/BN, S_DIM/BM, B_DIM*H_DIM), 256>>>(
        p_scores, p_kv + NOPE, p_attn, S_DIM, VD, S_DIM,
        S_DIM, H_DIM*(NOPE+VD), H_DIM*VD,
        (long long)H_DIM * S_DIM * S_DIM, (long long)S_DIM * S_DIM, // A strides
        (long long)S_DIM * H_DIM * (NOPE+VD), (long long)(NOPE+VD), // B strides
        (long long)S_DIM * H_DIM * VD, (long long)VD,               // C strides
        H_DIM);

    // 12. out = attn @ w_o  [4096,2048]@[2048,2048]
    sgemm_kernel<false,false><<<dim3(D_DIM/BN, T_DIM/BM, 1), 256>>>(
        p_attn, w_o, out, T_DIM, D_DIM, H_DIM*VD,
        H_DIM*VD, D_DIM, D_DIM,
        Z0,Z0,Z0,Z0,Z0,Z0, 1);
}

// round 2
// speedup vs baseline: 3.3645x; 3.3645x over previous
#include <cuda_runtime.h>
#include <cuda_bf16.h>
#include <math.h>

// ---------------- problem constants ----------------
#define T_DIM 4096
#define D_DIM 2048
#define H_DIM 16
#define NOPE 128
#define ROPE 64
#define VD 128
#define KV_RANK 512
#define HEAD 192               // NOPE + ROPE
#define Q_RANK 1536
#define B_DIM 2
#define S_DIM 2048
#define SCALE_F 0.072168783648703220563f   // 192^-0.5
#define EPS_F 1e-6f

// ---------------- scratch (device globals; no allocation allowed) ----------------
__device__ float g_qa  [(long long)T_DIM * Q_RANK];
__device__ float g_qan [(long long)T_DIM * Q_RANK];
__device__ float g_q   [(long long)T_DIM * H_DIM * HEAD];
__device__ float g_ckv [(long long)T_DIM * (KV_RANK + ROPE)];
__device__ float g_ckvn[(long long)T_DIM * KV_RANK];
__device__ float g_kv  [(long long)T_DIM * H_DIM * (NOPE + VD)];
__device__ float g_key [(long long)T_DIM * H_DIM * HEAD];
__device__ float g_scores[(long long)B_DIM * H_DIM * S_DIM * S_DIM]; // 536 MB
__device__ float g_attn[(long long)T_DIM * H_DIM * VD];

// ---------------- TF32 tensor-core batched GEMM ----------------
// C = A @ B (or A @ B^T). BM=BN=128, BK=32, 256 threads (8 warps),
// warp tile 64x32 via m16n8k8 tf32 mma. fp32 accumulate.
// cmode: 0 = none, 1 = PV (limit K to m0+BM), 2 = scores (skip blocks above diagonal)
#define BM 128
#define BN 128
#define BK 32
#define SA 36     // As row stride   (bank: 4*gr+tg unique)
#define SB 136    // Bs row stride   (bank: 8*tg+gr unique)

__device__ __forceinline__ unsigned tf32u(float f) {
    unsigned u; asm("cvt.rna.tf32.f32 %0, %1;" : "=r"(u) : "f"(f)); return u;
}

template<bool TRANS_B, bool GUARD_N>
__global__ void __launch_bounds__(256)
tgemm_kernel(const float* __restrict__ A, const float* __restrict__ B,
             float* __restrict__ C,
             int M, int N, int K, int lda, int ldb, int ldc,
             long long sAb, long long sAh,
             long long sBb, long long sBh,
             long long sCb, long long sCh, int Hdim, int cmode)
{
    int z  = blockIdx.z;
    int bb = z / Hdim, hh = z % Hdim;
    A += bb * sAb + hh * sAh;
    B += bb * sBb + hh * sBh;
    C += bb * sCb + hh * sCh;

    int m0 = blockIdx.y * BM;
    int n0 = blockIdx.x * BN;

    if (cmode == 2 && n0 >= m0 + BM) return;   // fully above diagonal
    int kEnd = (cmode == 1) ? min(K, m0 + BM) : K;

    __shared__ float As[BM * SA];              // [128][36]
    __shared__ float Bs[BM * SA];              // trans: [128][36], non-trans: [32][136]

    int tid  = threadIdx.x;
    int lane = tid & 31;
    int wid  = tid >> 5;
    int wm   = wid & 1;          // 2 warps along M (64 rows each)
    int wn   = wid >> 1;         // 4 warps along N (32 cols each)
    int gr   = lane >> 2;        // 0..7
    int tg   = lane & 3;         // 0..3

    float acc[4][4][4];
#pragma unroll
    for (int i = 0; i < 4; i++)
#pragma unroll
        for (int j = 0; j < 4; j++)
#pragma unroll
            for (int r = 0; r < 4; r++) acc[i][j][r] = 0.f;

    int ar  = tid >> 3;          // 0..31  (row within A tile per iter)
    int akq = (tid & 7) << 2;    // k offset 0,4,...,28

    for (int k0 = 0; k0 < kEnd; k0 += BK) {
        // ---- load A tile [128 x 32] -> As[r][k], tf32-rounded ----
#pragma unroll
        for (int it = 0; it < 4; it++) {
            int row = ar + it * 32;
            float4 v = *(const float4*)(A + (long long)(m0 + row) * lda + k0 + akq);
            float4 cv;
            cv.x = __uint_as_float(tf32u(v.x));
            cv.y = __uint_as_float(tf32u(v.y));
            cv.z = __uint_as_float(tf32u(v.z));
            cv.w = __uint_as_float(tf32u(v.w));
            *(float4*)&As[row * SA + akq] = cv;
        }
        // ---- load B tile ----
        if (TRANS_B) {
            // B is [N rows, K cols]: store Bs[n][k], stride SA
#pragma unroll
            for (int it = 0; it < 4; it++) {
                int row = ar + it * 32;
                float4 v = *(const float4*)(B + (long long)(n0 + row) * ldb + k0 + akq);
                float4 cv;
                cv.x = __uint_as_float(tf32u(v.x));
                cv.y = __uint_as_float(tf32u(v.y));
                cv.z = __uint_as_float(tf32u(v.z));
                cv.w = __uint_as_float(tf32u(v.w));
                *(float4*)&Bs[row * SA + akq] = cv;
            }
        } else {
            // B is [K rows, N cols]: store Bs[k][n], stride SB
            int bk  = tid >> 3;          // 0..31
            int bnq = (tid & 7) << 2;    // 0..28
#pragma unroll
            for (int it = 0; it < 4; it++) {
                int n = bnq + it * 32;
                float4 v = make_float4(0.f, 0.f, 0.f, 0.f);
                if (!GUARD_N || (n0 + n) < N)
                    v = *(const float4*)(B + (long long)(k0 + bk) * ldb + n0 + n);
                float4 cv;
                cv.x = __uint_as_float(tf32u(v.x));
                cv.y = __uint_as_float(tf32u(v.y));
                cv.z = __uint_as_float(tf32u(v.z));
                cv.w = __uint_as_float(tf32u(v.w));
                *(float4*)&Bs[bk * SB + n] = cv;
            }
        }
        __syncthreads();

        // ---- compute: 4 k8-steps ----
#pragma unroll
        for (int ks = 0; ks < 4; ks++) {
            int kk = ks * 8;
            unsigned af[4][4];
#pragma unroll
            for (int i = 0; i < 4; i++) {
                int r = wm * 64 + i * 16 + gr;
                af[i][0] = __float_as_uint(As[(r    ) * SA + kk + tg    ]);
                af[i][1] = __float_as_uint(As[(r + 8) * SA + kk + tg    ]);
                af[i][2] = __float_as_uint(As[(r    ) * SA + kk + tg + 4]);
                af[i][3] = __float_as_uint(As[(r + 8) * SA + kk + tg + 4]);
            }
            unsigned bf[4][2];
#pragma unroll
            for (int j = 0; j < 4; j++) {
                int c = wn * 32 + j * 8 + gr;
                if (TRANS_B) {
                    bf[j][0] = __float_as_uint(Bs[c * SA + kk + tg    ]);
                    bf[j][1] = __float_as_uint(Bs[c * SA + kk + tg + 4]);
                } else {
                    bf[j][0] = __float_as_uint(Bs[(kk + tg    ) * SB + c]);
                    bf[j][1] = __float_as_uint(Bs[(kk + tg + 4) * SB + c]);
                }
            }
#pragma unroll
            for (int i = 0; i < 4; i++)
#pragma unroll
                for (int j = 0; j < 4; j++) {
                    asm volatile(
                        "mma.sync.aligned.m16n8k8.row.col.f32.tf32.tf32.f32 "
                        "{%0,%1,%2,%3},{%4,%5,%6,%7},{%8,%9},{%0,%1,%2,%3};"
                        : "+f"(acc[i][j][0]), "+f"(acc[i][j][1]),
                          "+f"(acc[i][j][2]), "+f"(acc[i][j][3])
                        : "r"(af[i][0]), "r"(af[i][1]), "r"(af[i][2]), "r"(af[i][3]),
                          "r"(bf[j][0]), "r"(bf[j][1]));
                }
        }
        __syncthreads();
    }

    // ---- epilogue ----
#pragma unroll
    for (int i = 0; i < 4; i++) {
#pragma unroll
        for (int j = 0; j < 4; j++) {
            int r0 = m0 + wm * 64 + i * 16 + gr;
            int c  = n0 + wn * 32 + j * 8 + 2 * tg;
            if (!GUARD_N || c < N) {   // N is even at guarded sites
                float2 lo = make_float2(acc[i][j][0], acc[i][j][1]);
                float2 hi = make_float2(acc[i][j][2], acc[i][j][3]);
                *(float2*)(C + (long long)r0 * ldc + c)       = lo;
                *(float2*)(C + (long long)(r0 + 8) * ldc + c) = hi;
            }
        }
    }
}

// ---------------- rmsnorm (row-wise) ----------------
__global__ void rmsnorm_kernel(const float* __restrict__ x, const float* __restrict__ w,
                               float* __restrict__ y, int N, int ldx, int ldy)
{
    long long row = blockIdx.x;
    const float* xr = x + row * ldx;
    float* yr = y + row * ldy;
    int tid = threadIdx.x;

    float ss = 0.f;
    for (int i = tid; i < N; i += 256) { float v = xr[i]; ss += v * v; }

    __shared__ float red[256];
    red[tid] = ss; __syncthreads();
#pragma unroll
    for (int s = 128; s > 0; s >>= 1) {
        if (tid < s) red[tid] += red[tid + s];
        __syncthreads();
    }
    float sc = rsqrtf(red[0] / (float)N + EPS_F);
    for (int i = tid; i < N; i += 256) yr[i] = xr[i] * sc * w[i];
}

// ---------------- in-place RoPE on q (last 64 of each head) ----------------
__global__ void rope_q_kernel(float* __restrict__ q,
                              const float* __restrict__ cosp,
                              const float* __restrict__ sinp)
{
    int t = blockIdx.x, h = blockIdx.y, i = threadIdx.x;  // 32 threads
    float* pe = q + ((long long)t * H_DIM + h) * HEAD + NOPE;
    float e = pe[2 * i], o = pe[2 * i + 1];
    float c = cosp[t * 32 + i], s = sinp[t * 32 + i];
    __syncwarp();
    pe[i]      = e * c - o * s;
    pe[32 + i] = o * c + e * s;
}

// ---------------- build key[T,H,192] = concat(kv_nope, rope(k_pe)) ----------------
__global__ void build_key_kernel(const float* __restrict__ kv,
                                 const float* __restrict__ ckv,
                                 const float* __restrict__ cosp,
                                 const float* __restrict__ sinp,
                                 float* __restrict__ key)
{
    int t = blockIdx.x, h = blockIdx.y, tid = threadIdx.x;  // 128 threads
    float* kr = key + ((long long)t * H_DIM + h) * HEAD;
    kr[tid] = kv[(long long)t * (H_DIM * (NOPE + VD)) + h * (NOPE + VD) + tid];
    if (tid < 32) {
        const float* pe = ckv + (long long)t * (KV_RANK + ROPE) + KV_RANK;
        float e = pe[2 * tid], o = pe[2 * tid + 1];
        float c = cosp[t * 32 + tid], s = sinp[t * 32 + tid];
        kr[NOPE + tid]      = e * c - o * s;
        kr[NOPE + 32 + tid] = o * c + e * s;
    }
}

// ---------------- causal softmax over scores ----------------
// zeroes only up to the 128-aligned boundary (PV never reads past m0+128)
__global__ void softmax_kernel(float* __restrict__ scores)
{
    long long row = blockIdx.x;            // (b*H + h)*S + q
    int q = (int)(row % S_DIM);
    float* p = scores + row * (long long)S_DIM;
    int tid = threadIdx.x;
    __shared__ float red[256];

    float mx = -3.4e38f;
    for (int i = tid; i <= q; i += 256) mx = fmaxf(mx, p[i]);
    red[tid] = mx; __syncthreads();
#pragma unroll
    for (int s = 128; s > 0; s >>= 1) {
        if (tid < s) red[tid] = fmaxf(red[tid], red[tid + s]);
        __syncthreads();
    }
    mx = red[0] * SCALE_F;
    __syncthreads();

    float sum = 0.f;
    for (int i = tid; i <= q; i += 256) {
        float e = expf(p[i] * SCALE_F - mx);
        p[i] = e;
        sum += e;
    }
    red[tid] = sum; __syncthreads();
#pragma unroll
    for (int s = 128; s > 0; s >>= 1) {
        if (tid < s) red[tid] += red[tid + s];
        __syncthreads();
    }
    float inv = 1.0f / red[0];
    for (int i = tid; i <= q; i += 256) p[i] *= inv;
    int zend = ((q >> 7) + 1) << 7;          // round up to 128
    for (int i = q + 1 + tid; i < zend; i += 256) p[i] = 0.f;
}

// ---------------- launch ----------------
extern "C" void kernel_launch(void* const* d_in, const int* in_sizes, int n_in,
                              void* d_out, int out_size)
{
    const float* hidden   = (const float*)d_in[0];
    const float* cosp     = (const float*)d_in[1];
    const float* sinp     = (const float*)d_in[2];
    const float* w_q_a    = (const float*)d_in[3];
    const float* q_a_ln_w = (const float*)d_in[4];
    const float* w_q_b    = (const float*)d_in[5];
    const float* w_kv_a   = (const float*)d_in[6];
    const float* kv_a_ln_w= (const float*)d_in[7];
    const float* w_kv_b   = (const float*)d_in[8];
    const float* w_o      = (const float*)d_in[9];
    float* out = (float*)d_out;

    float *p_qa, *p_qan, *p_q, *p_ckv, *p_ckvn, *p_kv, *p_key, *p_scores, *p_attn;
    cudaGetSymbolAddress((void**)&p_qa,     g_qa);
    cudaGetSymbolAddress((void**)&p_qan,    g_qan);
    cudaGetSymbolAddress((void**)&p_q,      g_q);
    cudaGetSymbolAddress((void**)&p_ckv,    g_ckv);
    cudaGetSymbolAddress((void**)&p_ckvn,   g_ckvn);
    cudaGetSymbolAddress((void**)&p_kv,     g_kv);
    cudaGetSymbolAddress((void**)&p_key,    g_key);
    cudaGetSymbolAddress((void**)&p_scores, g_scores);
    cudaGetSymbolAddress((void**)&p_attn,   g_attn);

    const long long Z0 = 0;

    // 1. qa = hidden @ w_q_a   [4096,2048]@[2048,1536]
    tgemm_kernel<false,false><<<dim3(Q_RANK/BN, T_DIM/BM, 1), 256>>>(
        hidden, w_q_a, p_qa, T_DIM, Q_RANK, D_DIM, D_DIM, Q_RANK, Q_RANK,
        Z0,Z0,Z0,Z0,Z0,Z0, 1, 0);

    // 2. rmsnorm(qa)
    rmsnorm_kernel<<<T_DIM, 256>>>(p_qa, q_a_ln_w, p_qan, Q_RANK, Q_RANK, Q_RANK);

    // 3. q = qan @ w_q_b   [4096,1536]@[1536,3072]
    tgemm_kernel<false,false><<<dim3((H_DIM*HEAD)/BN, T_DIM/BM, 1), 256>>>(
        p_qan, w_q_b, p_q, T_DIM, H_DIM*HEAD, Q_RANK, Q_RANK, H_DIM*HEAD, H_DIM*HEAD,
        Z0,Z0,Z0,Z0,Z0,Z0, 1, 0);

    // 4. RoPE on q (in place)
    rope_q_kernel<<<dim3(T_DIM, H_DIM), 32>>>(p_q, cosp, sinp);

    // 5. ckv = hidden @ w_kv_a  [4096,2048]@[2048,576]  (N=576 guarded)
    tgemm_kernel<false,true><<<dim3((KV_RANK+ROPE+BN-1)/BN, T_DIM/BM, 1), 256>>>(
        hidden, w_kv_a, p_ckv, T_DIM, KV_RANK+ROPE, D_DIM, D_DIM, KV_RANK+ROPE, KV_RANK+ROPE,
        Z0,Z0,Z0,Z0,Z0,Z0, 1, 0);

    // 6. rmsnorm(ckv[:, :512])
    rmsnorm_kernel<<<T_DIM, 256>>>(p_ckv, kv_a_ln_w, p_ckvn, KV_RANK, KV_RANK+ROPE, KV_RANK);

    // 7. kv = ckvn @ w_kv_b   [4096,512]@[512,4096]
    tgemm_kernel<false,false><<<dim3((H_DIM*(NOPE+VD))/BN, T_DIM/BM, 1), 256>>>(
        p_ckvn, w_kv_b, p_kv, T_DIM, H_DIM*(NOPE+VD), KV_RANK,
        KV_RANK, H_DIM*(NOPE+VD), H_DIM*(NOPE+VD),
        Z0,Z0,Z0,Z0,Z0,Z0, 1, 0);

    // 8. build key
    build_key_kernel<<<dim3(T_DIM, H_DIM), 128>>>(p_kv, p_ckv, cosp, sinp, p_key);

    // 9. scores[b,h] = Q[b,:,h,:] @ K[b,:,h,:]^T   (NT, K=192, causal block skip)
    tgemm_kernel<true,false><<<dim3(S_DIM/BN, S_DIM/BM, B_DIM*H_DIM), 256>>>(
        p_q, p_key, p_scores, S_DIM, S_DIM, HEAD,
        H_DIM*HEAD, H_DIM*HEAD, S_DIM,
        (long long)S_DIM * H_DIM * HEAD, (long long)HEAD,
        (long long)S_DIM * H_DIM * HEAD, (long long)HEAD,
        (long long)H_DIM * S_DIM * S_DIM, (long long)S_DIM * S_DIM,
        H_DIM, 2);

    // 10. causal softmax (scale inside)
    softmax_kernel<<<B_DIM * H_DIM * S_DIM, 256>>>(p_scores);

    // 11. attn[b,:,h,:] = P[b,h] @ V[b,:,h,:]   (causal K-limit)
    tgemm_kernel<false,false><<<dim3(VD/BN, S_DIM/BM, B_DIM*H_DIM), 256>>>(
        p_scores, p_kv + NOPE, p_attn, S_DIM, VD, S_DIM,
        S_DIM, H_DIM*(NOPE+VD), H_DIM*VD,
        (long long)H_DIM * S_DIM * S_DIM, (long long)S_DIM * S_DIM,
        (long long)S_DIM * H_DIM * (NOPE+VD), (long long)(NOPE+VD),
        (long long)S_DIM * H_DIM * VD, (long long)VD,
        H_DIM, 1);

    // 12. out = attn @ w_o  [4096,2048]@[2048,2048]
    tgemm_kernel<false,false><<<dim3(D_DIM/BN, T_DIM/BM, 1), 256>>>(
        p_attn, w_o, out, T_DIM, D_DIM, H_DIM*VD,
        H_DIM*VD, D_DIM, D_DIM,
        Z0,Z0,Z0,Z0,Z0,Z0, 1, 0);
}

// round 3
// speedup vs baseline: 4.1076x; 1.2209x over previous
#include <cuda_runtime.h>
#include <cuda_bf16.h>
#include <math.h>

// ---------------- problem constants ----------------
#define T_DIM 4096
#define D_DIM 2048
#define H_DIM 16
#define NOPE 128
#define ROPE 64
#define VD 128
#define KV_RANK 512
#define HEAD 192               // NOPE + ROPE
#define Q_RANK 1536
#define B_DIM 2
#define S_DIM 2048
#define SCALE_F 0.072168783648703220563f   // 192^-0.5
#define EPS_F 1e-6f

// ---------------- scratch ----------------
__device__ float g_hid [(long long)T_DIM * D_DIM];
__device__ float g_qa  [(long long)T_DIM * Q_RANK];
__device__ float g_qan [(long long)T_DIM * Q_RANK];
__device__ float g_q   [(long long)T_DIM * H_DIM * HEAD];
__device__ float g_ckv [(long long)T_DIM * (KV_RANK + ROPE)];
__device__ float g_ckvn[(long long)T_DIM * KV_RANK];
__device__ float g_kv  [(long long)T_DIM * H_DIM * (NOPE + VD)];
__device__ float g_key [(long long)T_DIM * H_DIM * HEAD];
__device__ float g_scores[(long long)B_DIM * H_DIM * S_DIM * S_DIM];
__device__ float g_attn[(long long)T_DIM * H_DIM * VD];
// transposed (tf32-rounded) weights / V
__device__ float g_wqaT [(long long)Q_RANK * D_DIM];
__device__ float g_wqbT [(long long)H_DIM * HEAD * Q_RANK];
__device__ float g_wkvaT[(long long)(KV_RANK + ROPE) * D_DIM];
__device__ float g_wkvbT[(long long)H_DIM * (NOPE + VD) * KV_RANK];
__device__ float g_woT  [(long long)D_DIM * H_DIM * VD];
__device__ float g_vT   [(long long)B_DIM * H_DIM * VD * S_DIM];

__device__ __forceinline__ float tf32f(float f) {
    unsigned u; asm("cvt.rna.tf32.f32 %0, %1;" : "=r"(u) : "f"(f));
    return __uint_as_float(u);
}

__device__ __forceinline__ void cp16(unsigned dst, const void* src, bool v) {
    asm volatile("cp.async.cg.shared.global [%0], [%1], 16, %2;\n"
                 :: "r"(dst), "l"(src), "r"(v ? 16 : 0));
}
__device__ __forceinline__ void ldsm4(unsigned& r0, unsigned& r1, unsigned& r2, unsigned& r3,
                                      unsigned addr) {
    asm volatile("ldmatrix.sync.aligned.m8n8.x4.shared.b16 {%0,%1,%2,%3}, [%4];"
                 : "=r"(r0), "=r"(r1), "=r"(r2), "=r"(r3) : "r"(addr));
}

// ---------------- NT tf32 GEMM: C[m][n] = sum_k A[m][k]*B[n][k] ----------------
// 128x128x32 tile, 256 thr (8 warps: 2 along M x 4 along N), 3-stage cp.async,
// ldmatrix fragments. smem stage: A 128x36 floats + B 128x36 (stride 36 -> no conflicts).
// cmode: 0 none, 1 PV (K limited to m0+128), 2 scores (skip above diagonal)
#define STG_F 9216            // floats per stage (2*128*36)
#define STG_B 36864           // bytes per stage
#define BOFF_B 18432          // byte offset of B tile in stage

template<bool GUARD_N>
__global__ void __launch_bounds__(256, 2)
tgemm_kernel(const float* __restrict__ A, const float* __restrict__ B,
             float* __restrict__ C,
             int N, int K, int lda, int ldb, int ldc,
             long long sAb, long long sAh,
             long long sBb, long long sBh,
             long long sCb, long long sCh, int Hdim, int cmode, int round_out)
{
    extern __shared__ float sm[];
    int z  = blockIdx.z;
    int bb = z / Hdim, hh = z % Hdim;
    A += bb * sAb + hh * sAh;
    B += bb * sBb + hh * sBh;
    C += bb * sCb + hh * sCh;

    int m0 = blockIdx.y * 128;
    int n0 = blockIdx.x * 128;
    if (cmode == 2 && n0 >= m0 + 128) return;
    int kEnd = (cmode == 1) ? ((m0 + 128 < K) ? m0 + 128 : K) : K;
    int nIter = kEnd >> 5;

    int tid  = threadIdx.x;
    int lane = tid & 31;
    int wid  = tid >> 5;
    int wm   = wid & 1;
    int wn   = wid >> 1;

    unsigned sbase = (unsigned)__cvta_generic_to_shared(sm);
    int lrow = tid >> 3;     // 0..31
    int lc   = tid & 7;      // chunk 0..7

    auto issue = [&](int itk) {
        int k0 = itk << 5;
        unsigned sb = sbase + (unsigned)(itk % 3) * STG_B;
#pragma unroll
        for (int it = 0; it < 4; it++) {
            int row = lrow + it * 32;
            cp16(sb + row * 144 + lc * 16,
                 A + (long long)(m0 + row) * lda + k0 + lc * 4, true);
            int brow = n0 + row;
            bool v = (!GUARD_N) || (brow < N);
            cp16(sb + BOFF_B + row * 144 + lc * 16,
                 B + (long long)(v ? brow : 0) * ldb + k0 + lc * 4, v);
        }
        asm volatile("cp.async.commit_group;");
    };

    issue(0);
    issue(1);

    // fragment lane byte-offsets (within a stage)
    unsigned aoff[4], boff[2];
#pragma unroll
    for (int i = 0; i < 4; i++) {
        int R = wm * 64 + i * 16 + (lane & 15);
        aoff[i] = (unsigned)(R * 144 + (lane >> 4) * 16);
    }
#pragma unroll
    for (int jp = 0; jp < 2; jp++) {
        int R = wn * 32 + jp * 16 + ((lane >> 4) & 1) * 8 + (lane & 7);
        boff[jp] = (unsigned)(BOFF_B + R * 144 + ((lane >> 3) & 1) * 16);
    }

    float acc[4][4][4];
#pragma unroll
    for (int i = 0; i < 4; i++)
#pragma unroll
        for (int j = 0; j < 4; j++)
#pragma unroll
            for (int r = 0; r < 4; r++) acc[i][j][r] = 0.f;

    for (int i = 0; i < nIter; i++) {
        asm volatile("cp.async.wait_group 1;");
        __syncthreads();
        if (i + 2 < nIter) issue(i + 2);
        else asm volatile("cp.async.commit_group;");

        unsigned sb = sbase + (unsigned)(i % 3) * STG_B;
#pragma unroll
        for (int ks = 0; ks < 4; ks++) {
            unsigned af[4][4], bf[2][4];
#pragma unroll
            for (int ii = 0; ii < 4; ii++)
                ldsm4(af[ii][0], af[ii][1], af[ii][2], af[ii][3], sb + aoff[ii] + ks * 32);
#pragma unroll
            for (int jp = 0; jp < 2; jp++)
                ldsm4(bf[jp][0], bf[jp][1], bf[jp][2], bf[jp][3], sb + boff[jp] + ks * 32);
#pragma unroll
            for (int ii = 0; ii < 4; ii++)
#pragma unroll
                for (int j = 0; j < 4; j++) {
                    unsigned b0 = bf[j >> 1][(j & 1) * 2];
                    unsigned b1 = bf[j >> 1][(j & 1) * 2 + 1];
                    asm volatile(
                        "mma.sync.aligned.m16n8k8.row.col.f32.tf32.tf32.f32 "
                        "{%0,%1,%2,%3},{%4,%5,%6,%7},{%8,%9},{%0,%1,%2,%3};"
                        : "+f"(acc[ii][j][0]), "+f"(acc[ii][j][1]),
                          "+f"(acc[ii][j][2]), "+f"(acc[ii][j][3])
                        : "r"(af[ii][0]), "r"(af[ii][1]), "r"(af[ii][2]), "r"(af[ii][3]),
                          "r"(b0), "r"(b1));
                }
        }
    }

    int gr = lane >> 2, tg = lane & 3;
#pragma unroll
    for (int i = 0; i < 4; i++) {
#pragma unroll
        for (int j = 0; j < 4; j++) {
            long long r0 = m0 + wm * 64 + i * 16 + gr;
            int c = n0 + wn * 32 + j * 8 + 2 * tg;
            if (!GUARD_N || c < N) {
                float v0 = acc[i][j][0], v1 = acc[i][j][1];
                float v2 = acc[i][j][2], v3 = acc[i][j][3];
                if (round_out) { v0 = tf32f(v0); v1 = tf32f(v1); v2 = tf32f(v2); v3 = tf32f(v3); }
                *(float2*)(C + r0 * ldc + c)       = make_float2(v0, v1);
                *(float2*)(C + (r0 + 8) * ldc + c) = make_float2(v2, v3);
            }
        }
    }
}

// ---------------- transpose + tf32 round: out[n][k] = r(in[k][n]) ----------------
__global__ void transpose_round_kernel(const float* __restrict__ in, float* __restrict__ out,
                                       int K, int N)
{
    __shared__ float t[32][33];
    int n0 = blockIdx.x * 32, k0 = blockIdx.y * 32;
    int x = threadIdx.x, y = threadIdx.y;  // (32,8)
#pragma unroll
    for (int i = y; i < 32; i += 8)
        t[i][x] = in[(long long)(k0 + i) * N + n0 + x];
    __syncthreads();
#pragma unroll
    for (int i = y; i < 32; i += 8)
        out[(long long)(n0 + i) * K + k0 + x] = tf32f(t[x][i]);
}

// ---------------- V transpose: vT[b][h][d][s] = r(kv[b*S+s][h*256+128+d]) ----------------
__global__ void vtrans_kernel(const float* __restrict__ kv, float* __restrict__ vT)
{
    __shared__ float t[32][33];
    int z = blockIdx.z; int b = z >> 4, h = z & 15;
    int s0 = blockIdx.x * 32, d0 = blockIdx.y * 32;
    int x = threadIdx.x, y = threadIdx.y;
#pragma unroll
    for (int i = y; i < 32; i += 8)
        t[i][x] = kv[(long long)(b * S_DIM + s0 + i) * (H_DIM * 256) + h * 256 + 128 + d0 + x];
    __syncthreads();
#pragma unroll
    for (int i = y; i < 32; i += 8)
        vT[((long long)(b * H_DIM + h) * VD + d0 + i) * S_DIM + s0 + x] = tf32f(t[x][i]);
}

// ---------------- tf32 round-copy ----------------
__global__ void roundcpy_kernel(const float* __restrict__ in, float* __restrict__ out)
{
    long long i = ((long long)blockIdx.x * 256 + threadIdx.x) * 4;
    float4 v = *(const float4*)(in + i);
    v.x = tf32f(v.x); v.y = tf32f(v.y); v.z = tf32f(v.z); v.w = tf32f(v.w);
    *(float4*)(out + i) = v;
}

// ---------------- rmsnorm (tf32-rounded output) ----------------
__global__ void rmsnorm_kernel(const float* __restrict__ x, const float* __restrict__ w,
                               float* __restrict__ y, int N, int ldx, int ldy)
{
    long long row = blockIdx.x;
    const float* xr = x + row * ldx;
    float* yr = y + row * ldy;
    int tid = threadIdx.x;

    float ss = 0.f;
    for (int i = tid; i < N; i += 256) { float v = xr[i]; ss += v * v; }
    __shared__ float red[256];
    red[tid] = ss; __syncthreads();
#pragma unroll
    for (int s = 128; s > 0; s >>= 1) {
        if (tid < s) red[tid] += red[tid + s];
        __syncthreads();
    }
    float sc = rsqrtf(red[0] / (float)N + EPS_F);
    for (int i = tid; i < N; i += 256) yr[i] = tf32f(xr[i] * sc * w[i]);
}

// ---------------- RoPE on q (in place, rounded) ----------------
__global__ void rope_q_kernel(float* __restrict__ q,
                              const float* __restrict__ cosp,
                              const float* __restrict__ sinp)
{
    int t = blockIdx.x;
    int h = threadIdx.x >> 5, i = threadIdx.x & 31;   // 512 threads
    float* pe = q + ((long long)t * H_DIM + h) * HEAD + NOPE;
    float e = pe[2 * i], o = pe[2 * i + 1];
    float c = cosp[t * 32 + i], s = sinp[t * 32 + i];
    __syncwarp();
    pe[i]      = tf32f(e * c - o * s);
    pe[32 + i] = tf32f(o * c + e * s);
}

// ---------------- build key (rounded) ----------------
__global__ void build_key_kernel(const float* __restrict__ kv,
                                 const float* __restrict__ ckv,
                                 const float* __restrict__ cosp,
                                 const float* __restrict__ sinp,
                                 float* __restrict__ key)
{
    int t = blockIdx.x, h = blockIdx.y, tid = threadIdx.x;  // 128 threads
    float* kr = key + ((long long)t * H_DIM + h) * HEAD;
    kr[tid] = tf32f(kv[(long long)t * (H_DIM * 256) + h * 256 + tid]);
    if (tid < 32) {
        const float* pe = ckv + (long long)t * (KV_RANK + ROPE) + KV_RANK;
        float e = pe[2 * tid], o = pe[2 * tid + 1];
        float c = cosp[t * 32 + tid], s = sinp[t * 32 + tid];
        kr[NOPE + tid]      = tf32f(e * c - o * s);
        kr[NOPE + 32 + tid] = tf32f(o * c + e * s);
    }
}

// ---------------- causal softmax (rounded probs, zero to 128-boundary) ----------------
__global__ void softmax_kernel(float* __restrict__ scores)
{
    long long row = blockIdx.x;
    int q = (int)(row % S_DIM);
    float* p = scores + row * (long long)S_DIM;
    int tid = threadIdx.x;
    __shared__ float red[256];

    float mx = -3.4e38f;
    for (int i = tid; i <= q; i += 256) mx = fmaxf(mx, p[i]);
    red[tid] = mx; __syncthreads();
#pragma unroll
    for (int s = 128; s > 0; s >>= 1) {
        if (tid < s) red[tid] = fmaxf(red[tid], red[tid + s]);
        __syncthreads();
    }
    mx = red[0] * SCALE_F;
    __syncthreads();

    float sum = 0.f;
    for (int i = tid; i <= q; i += 256) {
        float e = expf(p[i] * SCALE_F - mx);
        p[i] = e;
        sum += e;
    }
    red[tid] = sum; __syncthreads();
#pragma unroll
    for (int s = 128; s > 0; s >>= 1) {
        if (tid < s) red[tid] += red[tid + s];
        __syncthreads();
    }
    float inv = 1.0f / red[0];
    for (int i = tid; i <= q; i += 256) p[i] = tf32f(p[i] * inv);
    int zend = ((q >> 7) + 1) << 7;
    for (int i = q + 1 + tid; i < zend; i += 256) p[i] = 0.f;
}

// ---------------- launch ----------------
extern "C" void kernel_launch(void* const* d_in, const int* in_sizes, int n_in,
                              void* d_out, int out_size)
{
    const float* hidden   = (const float*)d_in[0];
    const float* cosp     = (const float*)d_in[1];
    const float* sinp     = (const float*)d_in[2];
    const float* w_q_a    = (const float*)d_in[3];
    const float* q_a_ln_w = (const float*)d_in[4];
    const float* w_q_b    = (const float*)d_in[5];
    const float* w_kv_a   = (const float*)d_in[6];
    const float* kv_a_ln_w= (const float*)d_in[7];
    const float* w_kv_b   = (const float*)d_in[8];
    const float* w_o      = (const float*)d_in[9];
    float* out = (float*)d_out;

    float *p_hid, *p_qa, *p_qan, *p_q, *p_ckv, *p_ckvn, *p_kv, *p_key, *p_scores, *p_attn;
    float *p_wqaT, *p_wqbT, *p_wkvaT, *p_wkvbT, *p_woT, *p_vT;
    cudaGetSymbolAddress((void**)&p_hid,    g_hid);
    cudaGetSymbolAddress((void**)&p_qa,     g_qa);
    cudaGetSymbolAddress((void**)&p_qan,    g_qan);
    cudaGetSymbolAddress((void**)&p_q,      g_q);
    cudaGetSymbolAddress((void**)&p_ckv,    g_ckv);
    cudaGetSymbolAddress((void**)&p_ckvn,   g_ckvn);
    cudaGetSymbolAddress((void**)&p_kv,     g_kv);
    cudaGetSymbolAddress((void**)&p_key,    g_key);
    cudaGetSymbolAddress((void**)&p_scores, g_scores);
    cudaGetSymbolAddress((void**)&p_attn,   g_attn);
    cudaGetSymbolAddress((void**)&p_wqaT,   g_wqaT);
    cudaGetSymbolAddress((void**)&p_wqbT,   g_wqbT);
    cudaGetSymbolAddress((void**)&p_wkvaT,  g_wkvaT);
    cudaGetSymbolAddress((void**)&p_wkvbT,  g_wkvbT);
    cudaGetSymbolAddress((void**)&p_woT,    g_woT);
    cudaGetSymbolAddress((void**)&p_vT,     g_vT);

    const int SMEM = 3 * STG_B;   // 110592
    cudaFuncSetAttribute(tgemm_kernel<false>, cudaFuncAttributeMaxDynamicSharedMemorySize, SMEM);
    cudaFuncSetAttribute(tgemm_kernel<true>,  cudaFuncAttributeMaxDynamicSharedMemorySize, SMEM);

    const long long Z0 = 0;
    dim3 tb(32, 8);

    // --- pre-pass: round hidden, transpose+round all weights ---
    roundcpy_kernel<<<(T_DIM * D_DIM) / 1024, 256>>>(hidden, p_hid);
    transpose_round_kernel<<<dim3(Q_RANK/32, D_DIM/32), tb>>>(w_q_a,  p_wqaT,  D_DIM, Q_RANK);
    transpose_round_kernel<<<dim3((H_DIM*HEAD)/32, Q_RANK/32), tb>>>(w_q_b, p_wqbT, Q_RANK, H_DIM*HEAD);
    transpose_round_kernel<<<dim3((KV_RANK+ROPE)/32, D_DIM/32), tb>>>(w_kv_a, p_wkvaT, D_DIM, KV_RANK+ROPE);
    transpose_round_kernel<<<dim3((H_DIM*256)/32, KV_RANK/32), tb>>>(w_kv_b, p_wkvbT, KV_RANK, H_DIM*256);
    transpose_round_kernel<<<dim3(D_DIM/32, (H_DIM*VD)/32), tb>>>(w_o, p_woT, H_DIM*VD, D_DIM);

    // 1. qa = hid @ wqaT'
    tgemm_kernel<false><<<dim3(Q_RANK/128, T_DIM/128, 1), 256, SMEM>>>(
        p_hid, p_wqaT, p_qa, Q_RANK, D_DIM, D_DIM, D_DIM, Q_RANK,
        Z0,Z0,Z0,Z0,Z0,Z0, 1, 0, 0);

    // 2. rmsnorm(qa) -> qan (rounded)
    rmsnorm_kernel<<<T_DIM, 256>>>(p_qa, q_a_ln_w, p_qan, Q_RANK, Q_RANK, Q_RANK);

    // 3. q = qan @ wqbT'  (rounded out)
    tgemm_kernel<false><<<dim3((H_DIM*HEAD)/128, T_DIM/128, 1), 256, SMEM>>>(
        p_qan, p_wqbT, p_q, H_DIM*HEAD, Q_RANK, Q_RANK, Q_RANK, H_DIM*HEAD,
        Z0,Z0,Z0,Z0,Z0,Z0, 1, 0, 1);

    // 4. rope q (rounded)
    rope_q_kernel<<<T_DIM, 512>>>(p_q, cosp, sinp);

    // 5. ckv = hid @ wkvaT'  (N=576 guarded)
    tgemm_kernel<true><<<dim3(5, T_DIM/128, 1), 256, SMEM>>>(
        p_hid, p_wkvaT, p_ckv, KV_RANK+ROPE, D_DIM, D_DIM, D_DIM, KV_RANK+ROPE,
        Z0,Z0,Z0,Z0,Z0,Z0, 1, 0, 0);

    // 6. rmsnorm(ckv[:, :512]) -> ckvn (rounded)
    rmsnorm_kernel<<<T_DIM, 256>>>(p_ckv, kv_a_ln_w, p_ckvn, KV_RANK, KV_RANK+ROPE, KV_RANK);

    // 7. kv = ckvn @ wkvbT'
    tgemm_kernel<false><<<dim3((H_DIM*256)/128, T_DIM/128, 1), 256, SMEM>>>(
        p_ckvn, p_wkvbT, p_kv, H_DIM*256, KV_RANK, KV_RANK, KV_RANK, H_DIM*256,
        Z0,Z0,Z0,Z0,Z0,Z0, 1, 0, 0);

    // 8. build key (rounded); transpose V (rounded)
    build_key_kernel<<<dim3(T_DIM, H_DIM), 128>>>(p_kv, p_ckv, cosp, sinp, p_key);
    vtrans_kernel<<<dim3(S_DIM/32, VD/32, B_DIM*H_DIM), tb>>>(p_kv, p_vT);

    // 9. scores = q @ key^T  (causal block skip)
    tgemm_kernel<false><<<dim3(S_DIM/128, S_DIM/128, B_DIM*H_DIM), 256, SMEM>>>(
        p_q, p_key, p_scores, S_DIM, HEAD,
        H_DIM*HEAD, H_DIM*HEAD, S_DIM,
        (long long)S_DIM * H_DIM * HEAD, (long long)HEAD,
        (long long)S_DIM * H_DIM * HEAD, (long long)HEAD,
        (long long)H_DIM * S_DIM * S_DIM, (long long)S_DIM * S_DIM,
        H_DIM, 2, 0);

    // 10. softmax (rounded probs)
    softmax_kernel<<<B_DIM * H_DIM * S_DIM, 256>>>(p_scores);

    // 11. attn = probs @ vT'  (causal K-limit, rounded out)
    tgemm_kernel<false><<<dim3(1, S_DIM/128, B_DIM*H_DIM), 256, SMEM>>>(
        p_scores, p_vT, p_attn, VD, S_DIM,
        S_DIM, S_DIM, H_DIM*VD,
        (long long)H_DIM * S_DIM * S_DIM, (long long)S_DIM * S_DIM,
        (long long)H_DIM * VD * S_DIM, (long long)VD * S_DIM,
        (long long)S_DIM * H_DIM * VD, (long long)VD,
        H_DIM, 1, 1);

    // 12. out = attn @ woT'
    tgemm_kernel<false><<<dim3(D_DIM/128, T_DIM/128, 1), 256, SMEM>>>(
        p_attn, p_woT, out, D_DIM, H_DIM*VD, H_DIM*VD, H_DIM*VD, D_DIM,
        Z0,Z0,Z0,Z0,Z0,Z0, 1, 0, 0);
}

// round 5
// speedup vs baseline: 4.2363x; 1.0313x over previous
#include <cuda_runtime.h>
#include <cuda_bf16.h>
#include <math.h>

// ---------------- problem constants ----------------
#define T_DIM 4096
#define D_DIM 2048
#define H_DIM 16
#define NOPE 128
#define ROPE 64
#define VD 128
#define KV_RANK 512
#define HEAD 192               // NOPE + ROPE
#define Q_RANK 1536
#define B_DIM 2
#define S_DIM 2048
#define SCALE_F 0.072168783648703220563f   // 192^-0.5
#define EPS_F 1e-6f

// ---------------- scratch ----------------
__device__ float g_hid [(long long)T_DIM * D_DIM];
__device__ float g_qa  [(long long)T_DIM * Q_RANK];
__device__ float g_qan [(long long)T_DIM * Q_RANK];
__device__ float g_q   [(long long)T_DIM * H_DIM * HEAD];
__device__ float g_ckv [(long long)T_DIM * (KV_RANK + ROPE)];
__device__ float g_ckvn[(long long)T_DIM * KV_RANK];
__device__ float g_kv  [(long long)T_DIM * H_DIM * (NOPE + VD)];
__device__ float g_key [(long long)T_DIM * H_DIM * HEAD];
__device__ float g_scores[(long long)B_DIM * H_DIM * S_DIM * S_DIM];
__device__ float g_attn[(long long)T_DIM * H_DIM * VD];
// transposed (tf32-rounded) weights / V
__device__ float g_wqaT [(long long)Q_RANK * D_DIM];
__device__ float g_wqbT [(long long)H_DIM * HEAD * Q_RANK];
__device__ float g_wkvaT[(long long)(KV_RANK + ROPE + 64) * D_DIM];
__device__ float g_wkvbT[(long long)H_DIM * (NOPE + VD) * KV_RANK];
__device__ float g_woT  [(long long)D_DIM * H_DIM * VD];
__device__ float g_vT   [(long long)B_DIM * H_DIM * VD * S_DIM];

__device__ __forceinline__ float tf32f(float f) {
    unsigned u; asm("cvt.rna.tf32.f32 %0, %1;" : "=r"(u) : "f"(f));
    return __uint_as_float(u);
}

__device__ __forceinline__ void cp16(unsigned dst, const void* src, bool v) {
    asm volatile("cp.async.cg.shared.global [%0], [%1], 16, %2;\n"
                 :: "r"(dst), "l"(src), "r"(v ? 16 : 0));
}
__device__ __forceinline__ void ldsm4(unsigned& r0, unsigned& r1, unsigned& r2, unsigned& r3,
                                      unsigned addr) {
    asm volatile("ldmatrix.sync.aligned.m8n8.x4.shared.b16 {%0,%1,%2,%3}, [%4];"
                 : "=r"(r0), "=r"(r1), "=r"(r2), "=r"(r3) : "r"(addr));
}

// ---------------- NT tf32 GEMM (same as R3, proven) ----------------
#define STG_F 9216
#define STG_B 36864
#define BOFF_B 18432

template<bool GUARD_N>
__global__ void __launch_bounds__(256, 2)
tgemm_kernel(const float* __restrict__ A, const float* __restrict__ B,
             float* __restrict__ C,
             int N, int K, int lda, int ldb, int ldc,
             long long sAb, long long sAh,
             long long sBb, long long sBh,
             long long sCb, long long sCh, int Hdim, int cmode, int round_out)
{
    extern __shared__ float sm[];
    int z  = blockIdx.z;
    int bb = z / Hdim, hh = z % Hdim;
    A += bb * sAb + hh * sAh;
    B += bb * sBb + hh * sBh;
    C += bb * sCb + hh * sCh;

    int m0 = blockIdx.y * 128;
    int n0 = blockIdx.x * 128;
    if (cmode == 2 && n0 >= m0 + 128) return;
    int kEnd = (cmode == 1) ? ((m0 + 128 < K) ? m0 + 128 : K) : K;
    int nIter = kEnd >> 5;

    int tid  = threadIdx.x;
    int lane = tid & 31;
    int wid  = tid >> 5;
    int wm   = wid & 1;
    int wn   = wid >> 1;

    unsigned sbase = (unsigned)__cvta_generic_to_shared(sm);
    int lrow = tid >> 3;
    int lc   = tid & 7;

    auto issue = [&](int itk) {
        int k0 = itk << 5;
        unsigned sb = sbase + (unsigned)(itk % 3) * STG_B;
#pragma unroll
        for (int it = 0; it < 4; it++) {
            int row = lrow + it * 32;
            cp16(sb + row * 144 + lc * 16,
                 A + (long long)(m0 + row) * lda + k0 + lc * 4, true);
            int brow = n0 + row;
            bool v = (!GUARD_N) || (brow < N);
            cp16(sb + BOFF_B + row * 144 + lc * 16,
                 B + (long long)(v ? brow : 0) * ldb + k0 + lc * 4, v);
        }
        asm volatile("cp.async.commit_group;");
    };

    issue(0);
    issue(1);

    unsigned aoff[4], boff[2];
#pragma unroll
    for (int i = 0; i < 4; i++) {
        int R = wm * 64 + i * 16 + (lane & 15);
        aoff[i] = (unsigned)(R * 144 + (lane >> 4) * 16);
    }
#pragma unroll
    for (int jp = 0; jp < 2; jp++) {
        int R = wn * 32 + jp * 16 + ((lane >> 4) & 1) * 8 + (lane & 7);
        boff[jp] = (unsigned)(BOFF_B + R * 144 + ((lane >> 3) & 1) * 16);
    }

    float acc[4][4][4];
#pragma unroll
    for (int i = 0; i < 4; i++)
#pragma unroll
        for (int j = 0; j < 4; j++)
#pragma unroll
            for (int r = 0; r < 4; r++) acc[i][j][r] = 0.f;

    for (int i = 0; i < nIter; i++) {
        asm volatile("cp.async.wait_group 1;");
        __syncthreads();
        if (i + 2 < nIter) issue(i + 2);
        else asm volatile("cp.async.commit_group;");

        unsigned sb = sbase + (unsigned)(i % 3) * STG_B;
#pragma unroll
        for (int ks = 0; ks < 4; ks++) {
            unsigned af[4][4], bf[2][4];
#pragma unroll
            for (int ii = 0; ii < 4; ii++)
                ldsm4(af[ii][0], af[ii][1], af[ii][2], af[ii][3], sb + aoff[ii] + ks * 32);
#pragma unroll
            for (int jp = 0; jp < 2; jp++)
                ldsm4(bf[jp][0], bf[jp][1], bf[jp][2], bf[jp][3], sb + boff[jp] + ks * 32);
#pragma unroll
            for (int ii = 0; ii < 4; ii++)
#pragma unroll
                for (int j = 0; j < 4; j++) {
                    unsigned b0 = bf[j >> 1][(j & 1) * 2];
                    unsigned b1 = bf[j >> 1][(j & 1) * 2 + 1];
                    asm volatile(
                        "mma.sync.aligned.m16n8k8.row.col.f32.tf32.tf32.f32 "
                        "{%0,%1,%2,%3},{%4,%5,%6,%7},{%8,%9},{%0,%1,%2,%3};"
                        : "+f"(acc[ii][j][0]), "+f"(acc[ii][j][1]),
                          "+f"(acc[ii][j][2]), "+f"(acc[ii][j][3])
                        : "r"(af[ii][0]), "r"(af[ii][1]), "r"(af[ii][2]), "r"(af[ii][3]),
                          "r"(b0), "r"(b1));
                }
        }
    }

    int gr = lane >> 2, tg = lane & 3;
#pragma unroll
    for (int i = 0; i < 4; i++) {
#pragma unroll
        for (int j = 0; j < 4; j++) {
            long long r0 = m0 + wm * 64 + i * 16 + gr;
            int c = n0 + wn * 32 + j * 8 + 2 * tg;
            if (!GUARD_N || c < N) {
                float v0 = acc[i][j][0], v1 = acc[i][j][1];
                float v2 = acc[i][j][2], v3 = acc[i][j][3];
                if (round_out) { v0 = tf32f(v0); v1 = tf32f(v1); v2 = tf32f(v2); v3 = tf32f(v3); }
                *(float2*)(C + r0 * ldc + c)       = make_float2(v0, v1);
                *(float2*)(C + (r0 + 8) * ldc + c) = make_float2(v2, v3);
            }
        }
    }
}

// ---------------- merged pre-pass: hidden round-copy + 5 weight transposes ----------------
// tile map (32x32 tiles / 1024-elem copy tiles):
//   [0, 8192)        hidden round-copy
//   [8192, 11264)    w_q_a  T (K=2048, N=1536)
//   [11264, 15872)   w_q_b  T (K=1536, N=3072)
//   [15872, 17024)   w_kv_a T (K=2048, N=576)
//   [17024, 19072)   w_kv_b T (K=512,  N=4096)
//   [19072, 23168)   w_o    T (K=2048, N=2048)
__global__ void __launch_bounds__(256)
prep_kernel(const float* __restrict__ hidden,
            const float* __restrict__ w_q_a, const float* __restrict__ w_q_b,
            const float* __restrict__ w_kv_a, const float* __restrict__ w_kv_b,
            const float* __restrict__ w_o,
            float* __restrict__ hid,
            float* __restrict__ wqaT, float* __restrict__ wqbT,
            float* __restrict__ wkvaT, float* __restrict__ wkvbT,
            float* __restrict__ woT)
{
    int tile = blockIdx.x;
    int tid = threadIdx.x;

    if (tile < 8192) {   // hidden copy
        long long o = (long long)tile * 1024 + tid * 4;
        float4 v = *(const float4*)(hidden + o);
        v.x = tf32f(v.x); v.y = tf32f(v.y); v.z = tf32f(v.z); v.w = tf32f(v.w);
        *(float4*)(hid + o) = v;
        return;
    }

    const float* in; float* out; int K, N, idx;
    if (tile < 11264)      { in = w_q_a;  out = wqaT;  K = 2048; N = 1536; idx = tile - 8192; }
    else if (tile < 15872) { in = w_q_b;  out = wqbT;  K = 1536; N = 3072; idx = tile - 11264; }
    else if (tile < 17024) { in = w_kv_a; out = wkvaT; K = 2048; N = 576;  idx = tile - 15872; }
    else if (tile < 19072) { in = w_kv_b; out = wkvbT; K = 512;  N = 4096; idx = tile - 17024; }
    else                   { in = w_o;    out = woT;   K = 2048; N = 2048; idx = tile - 19072; }

    int nx = N >> 5;
    int n0 = (idx % nx) * 32;
    int k0 = (idx / nx) * 32;

    __shared__ float t[32][33];
    int x = tid & 31, y = tid >> 5;   // (32, 8)
#pragma unroll
    for (int i = y; i < 32; i += 8)
        t[i][x] = in[(long long)(k0 + i) * N + n0 + x];
    __syncthreads();
#pragma unroll
    for (int i = y; i < 32; i += 8)
        out[(long long)(n0 + i) * K + k0 + x] = tf32f(t[x][i]);
}

// ---------------- V transpose (rounded) ----------------
__global__ void vtrans_kernel(const float* __restrict__ kv, float* __restrict__ vT)
{
    __shared__ float t[32][33];
    int z = blockIdx.z; int b = z >> 4, h = z & 15;
    int s0 = blockIdx.x * 32, d0 = blockIdx.y * 32;
    int x = threadIdx.x, y = threadIdx.y;
#pragma unroll
    for (int i = y; i < 32; i += 8)
        t[i][x] = kv[(long long)(b * S_DIM + s0 + i) * (H_DIM * 256) + h * 256 + 128 + d0 + x];
    __syncthreads();
#pragma unroll
    for (int i = y; i < 32; i += 8)
        vT[((long long)(b * H_DIM + h) * VD + d0 + i) * S_DIM + s0 + x] = tf32f(t[x][i]);
}

// ---------------- rmsnorm (float4, rounded out) ----------------
__global__ void rmsnorm_kernel(const float* __restrict__ x, const float* __restrict__ w,
                               float* __restrict__ y, int N, int ldx, int ldy)
{
    long long row = blockIdx.x;
    const float4* xr = (const float4*)(x + row * ldx);
    const float4* wr = (const float4*)w;
    float4* yr = (float4*)(y + row * ldy);
    int tid = threadIdx.x;
    int nv = N >> 2;

    float ss = 0.f;
    for (int i = tid; i < nv; i += 256) {
        float4 v = xr[i];
        ss += v.x * v.x + v.y * v.y + v.z * v.z + v.w * v.w;
    }
    __shared__ float red[256];
    red[tid] = ss; __syncthreads();
#pragma unroll
    for (int s = 128; s > 0; s >>= 1) {
        if (tid < s) red[tid] += red[tid + s];
        __syncthreads();
    }
    float sc = rsqrtf(red[0] / (float)N + EPS_F);
    for (int i = tid; i < nv; i += 256) {
        float4 v = xr[i], ww = wr[i];
        v.x = tf32f(v.x * sc * ww.x); v.y = tf32f(v.y * sc * ww.y);
        v.z = tf32f(v.z * sc * ww.z); v.w = tf32f(v.w * sc * ww.w);
        yr[i] = v;
    }
}

// ---------------- RoPE on q (in place, rounded) ----------------
__global__ void rope_q_kernel(float* __restrict__ q,
                              const float* __restrict__ cosp,
                              const float* __restrict__ sinp)
{
    int t = blockIdx.x;
    int h = threadIdx.x >> 5, i = threadIdx.x & 31;   // 512 threads
    float* pe = q + ((long long)t * H_DIM + h) * HEAD + NOPE;
    float e = pe[2 * i], o = pe[2 * i + 1];
    float c = cosp[t * 32 + i], s = sinp[t * 32 + i];
    __syncwarp();
    pe[i]      = tf32f(e * c - o * s);
    pe[32 + i] = tf32f(o * c + e * s);
}

// ---------------- build key (rounded) ----------------
__global__ void build_key_kernel(const float* __restrict__ kv,
                                 const float* __restrict__ ckv,
                                 const float* __restrict__ cosp,
                                 const float* __restrict__ sinp,
                                 float* __restrict__ key)
{
    int t = blockIdx.x, h = blockIdx.y, tid = threadIdx.x;  // 128 threads
    float* kr = key + ((long long)t * H_DIM + h) * HEAD;
    kr[tid] = tf32f(kv[(long long)t * (H_DIM * 256) + h * 256 + tid]);
    if (tid < 32) {
        const float* pe = ckv + (long long)t * (KV_RANK + ROPE) + KV_RANK;
        float e = pe[2 * tid], o = pe[2 * tid + 1];
        float c = cosp[t * 32 + tid], s = sinp[t * 32 + tid];
        kr[NOPE + tid]      = tf32f(e * c - o * s);
        kr[NOPE + 32 + tid] = tf32f(o * c + e * s);
    }
}

// ---------------- causal softmax (float4, rounded probs) ----------------
__global__ void softmax_kernel(float* __restrict__ scores)
{
    long long row = blockIdx.x;
    int q = (int)(row % S_DIM);
    float* p = scores + row * (long long)S_DIM;
    float4* p4 = (float4*)p;
    int tid = threadIdx.x;
    __shared__ float red[256];

    int nv = (q + 1) >> 2;        // full float4 chunks within [0, q]
    int rem = (q + 1) & 3;

    float mx = -3.4e38f;
    for (int i = tid; i < nv; i += 256) {
        float4 v = p4[i];
        mx = fmaxf(mx, fmaxf(fmaxf(v.x, v.y), fmaxf(v.z, v.w)));
    }
    if (tid < rem) mx = fmaxf(mx, p[nv * 4 + tid]);
    red[tid] = mx; __syncthreads();
#pragma unroll
    for (int s = 128; s > 0; s >>= 1) {
        if (tid < s) red[tid] = fmaxf(red[tid], red[tid + s]);
        __syncthreads();
    }
    mx = red[0] * SCALE_F;
    __syncthreads();

    float sum = 0.f;
    for (int i = tid; i < nv; i += 256) {
        float4 v = p4[i];
        v.x = expf(v.x * SCALE_F - mx); v.y = expf(v.y * SCALE_F - mx);
        v.z = expf(v.z * SCALE_F - mx); v.w = expf(v.w * SCALE_F - mx);
        p4[i] = v;
        sum += v.x + v.y + v.z + v.w;
    }
    if (tid < rem) {
        float e = expf(p[nv * 4 + tid] * SCALE_F - mx);
        p[nv * 4 + tid] = e;
        sum += e;
    }
    red[tid] = sum; __syncthreads();
#pragma unroll
    for (int s = 128; s > 0; s >>= 1) {
        if (tid < s) red[tid] += red[tid + s];
        __syncthreads();
    }
    float inv = 1.0f / red[0];
    for (int i = tid; i < nv; i += 256) {
        float4 v = p4[i];
        v.x = tf32f(v.x * inv); v.y = tf32f(v.y * inv);
        v.z = tf32f(v.z * inv); v.w = tf32f(v.w * inv);
        p4[i] = v;
    }
    if (tid < rem) p[nv * 4 + tid] = tf32f(p[nv * 4 + tid] * inv);
    int zend = ((q >> 7) + 1) << 7;
    for (int i = q + 1 + tid; i < zend; i += 256) p[i] = 0.f;
}

// ---------------- launch ----------------
extern "C" void kernel_launch(void* const* d_in, const int* in_sizes, int n_in,
                              void* d_out, int out_size)
{
    const float* hidden   = (const float*)d_in[0];
    const float* cosp     = (const float*)d_in[1];
    const float* sinp     = (const float*)d_in[2];
    const float* w_q_a    = (const float*)d_in[3];
    const float* q_a_ln_w = (const float*)d_in[4];
    const float* w_q_b    = (const float*)d_in[5];
    const float* w_kv_a   = (const float*)d_in[6];
    const float* kv_a_ln_w= (const float*)d_in[7];
    const float* w_kv_b   = (const float*)d_in[8];
    const float* w_o      = (const float*)d_in[9];
    float* out = (float*)d_out;

    float *p_hid, *p_qa, *p_qan, *p_q, *p_ckv, *p_ckvn, *p_kv, *p_key, *p_scores, *p_attn;
    float *p_wqaT, *p_wqbT, *p_wkvaT, *p_wkvbT, *p_woT, *p_vT;
    cudaGetSymbolAddress((void**)&p_hid,    g_hid);
    cudaGetSymbolAddress((void**)&p_qa,     g_qa);
    cudaGetSymbolAddress((void**)&p_qan,    g_qan);
    cudaGetSymbolAddress((void**)&p_q,      g_q);
    cudaGetSymbolAddress((void**)&p_ckv,    g_ckv);
    cudaGetSymbolAddress((void**)&p_ckvn,   g_ckvn);
    cudaGetSymbolAddress((void**)&p_kv,     g_kv);
    cudaGetSymbolAddress((void**)&p_key,    g_key);
    cudaGetSymbolAddress((void**)&p_scores, g_scores);
    cudaGetSymbolAddress((void**)&p_attn,   g_attn);
    cudaGetSymbolAddress((void**)&p_wqaT,   g_wqaT);
    cudaGetSymbolAddress((void**)&p_wqbT,   g_wqbT);
    cudaGetSymbolAddress((void**)&p_wkvaT,  g_wkvaT);
    cudaGetSymbolAddress((void**)&p_wkvbT,  g_wkvbT);
    cudaGetSymbolAddress((void**)&p_woT,    g_woT);
    cudaGetSymbolAddress((void**)&p_vT,     g_vT);

    const int SMEM = 3 * STG_B;
    cudaFuncSetAttribute(tgemm_kernel<false>, cudaFuncAttributeMaxDynamicSharedMemorySize, SMEM);
    cudaFuncSetAttribute(tgemm_kernel<true>,  cudaFuncAttributeMaxDynamicSharedMemorySize, SMEM);

    const long long Z0 = 0;
    dim3 tb(32, 8);

    // launch 1: merged pre-pass
    prep_kernel<<<23168, 256>>>(hidden, w_q_a, w_q_b, w_kv_a, w_kv_b, w_o,
                                p_hid, p_wqaT, p_wqbT, p_wkvaT, p_wkvbT, p_woT);

    // launch 2: qa = hid @ wqaT'
    tgemm_kernel<false><<<dim3(Q_RANK/128, T_DIM/128, 1), 256, SMEM>>>(
        p_hid, p_wqaT, p_qa, Q_RANK, D_DIM, D_DIM, D_DIM, Q_RANK,
        Z0,Z0,Z0,Z0,Z0,Z0, 1, 0, 0);

    // launch 3: rmsnorm(qa)
    rmsnorm_kernel<<<T_DIM, 256>>>(p_qa, q_a_ln_w, p_qan, Q_RANK, Q_RANK, Q_RANK);

    // launch 4: q = qan @ wqbT'  (rounded out)
    tgemm_kernel<false><<<dim3((H_DIM*HEAD)/128, T_DIM/128, 1), 256, SMEM>>>(
        p_qan, p_wqbT, p_q, H_DIM*HEAD, Q_RANK, Q_RANK, Q_RANK, H_DIM*HEAD,
        Z0,Z0,Z0,Z0,Z0,Z0, 1, 0, 1);

    // launch 5: rope q
    rope_q_kernel<<<T_DIM, 512>>>(p_q, cosp, sinp);

    // launch 6 (ncu target): ckv = hid @ wkvaT'  (N=576 guarded)
    tgemm_kernel<true><<<dim3(5, T_DIM/128, 1), 256, SMEM>>>(
        p_hid, p_wkvaT, p_ckv, KV_RANK+ROPE, D_DIM, D_DIM, D_DIM, KV_RANK+ROPE,
        Z0,Z0,Z0,Z0,Z0,Z0, 1, 0, 0);

    // rmsnorm(ckv[:, :512])
    rmsnorm_kernel<<<T_DIM, 256>>>(p_ckv, kv_a_ln_w, p_ckvn, KV_RANK, KV_RANK+ROPE, KV_RANK);

    // kv = ckvn @ wkvbT'
    tgemm_kernel<false><<<dim3((H_DIM*256)/128, T_DIM/128, 1), 256, SMEM>>>(
        p_ckvn, p_wkvbT, p_kv, H_DIM*256, KV_RANK, KV_RANK, KV_RANK, H_DIM*256,
        Z0,Z0,Z0,Z0,Z0,Z0, 1, 0, 0);

    // build key; transpose V
    build_key_kernel<<<dim3(T_DIM, H_DIM), 128>>>(p_kv, p_ckv, cosp, sinp, p_key);
    vtrans_kernel<<<dim3(S_DIM/32, VD/32, B_DIM*H_DIM), tb>>>(p_kv, p_vT);

    // scores = q @ key^T  (causal block skip)
    tgemm_kernel<false><<<dim3(S_DIM/128, S_DIM/128, B_DIM*H_DIM), 256, SMEM>>>(
        p_q, p_key, p_scores, S_DIM, HEAD,
        H_DIM*HEAD, H_DIM*HEAD, S_DIM,
        (long long)S_DIM * H_DIM * HEAD, (long long)HEAD,
        (long long)S_DIM * H_DIM * HEAD, (long long)HEAD,
        (long long)H_DIM * S_DIM * S_DIM, (long long)S_DIM * S_DIM,
        H_DIM, 2, 0);

    // softmax
    softmax_kernel<<<B_DIM * H_DIM * S_DIM, 256>>>(p_scores);

    // attn = probs @ vT'  (causal K-limit, rounded out)
    tgemm_kernel<false><<<dim3(1, S_DIM/128, B_DIM*H_DIM), 256, SMEM>>>(
        p_scores, p_vT, p_attn, VD, S_DIM,
        S_DIM, S_DIM, H_DIM*VD,
        (long long)H_DIM * S_DIM * S_DIM, (long long)S_DIM * S_DIM,
        (long long)H_DIM * VD * S_DIM, (long long)VD * S_DIM,
        (long long)S_DIM * H_DIM * VD, (long long)VD,
        H_DIM, 1, 1);

    // out = attn @ woT'
    tgemm_kernel<false><<<dim3(D_DIM/128, T_DIM/128, 1), 256, SMEM>>>(
        p_attn, p_woT, out, D_DIM, H_DIM*VD, H_DIM*VD, H_DIM*VD, D_DIM,
        Z0,Z0,Z0,Z0,Z0,Z0, 1, 0, 0);
}